// round 4
// baseline (speedup 1.0000x reference)
#include <cuda_runtime.h>
#include <cstdint>

#define B_  8
#define L_  1024
#define D_  256
#define H_  8
#define HD_ 2048
#define F_  1024
#define ROWS_ (B_*L_)
#define EPS_ 1e-5f

// --------------------------- scratch (device globals) ------------------------
__device__ float g_Q[(size_t)ROWS_ * HD_];
__device__ float g_K[(size_t)ROWS_ * HD_];
__device__ float g_V[(size_t)ROWS_ * HD_];
__device__ float g_S[(size_t)B_ * H_ * L_ * L_];
__device__ float g_O[(size_t)ROWS_ * HD_];
__device__ float g_R1[(size_t)ROWS_ * D_];
__device__ float g_Z1[(size_t)ROWS_ * D_];   // exact LN1 out (residual)
__device__ float g_Z1r[(size_t)ROWS_ * D_];  // tf32-rounded LN1 out (GEMM A)
__device__ float g_Hb[(size_t)ROWS_ * F_];
__device__ float g_F[(size_t)ROWS_ * D_];
// tf32-rounded copies of inputs
__device__ float g_xr[(size_t)ROWS_ * D_];
__device__ float g_Wqr[(size_t)HD_ * D_];
__device__ float g_Wkr[(size_t)HD_ * D_];
__device__ float g_Wvr[(size_t)HD_ * D_];
__device__ float g_Wur[(size_t)D_ * HD_];
__device__ float g_W1r[(size_t)F_ * D_];
__device__ float g_W2r[(size_t)D_ * F_];

// --------------------------- helpers ----------------------------------------
__device__ __forceinline__ uint32_t f2tf(float f) {
    uint32_t u;
    asm("cvt.rna.tf32.f32 %0, %1;" : "=r"(u) : "f"(f));
    return u;
}
__device__ __forceinline__ float f2tf_f(float f) {
    return __uint_as_float(f2tf(f));
}
__device__ __forceinline__ void mma8(float* c, const uint32_t* a, const uint32_t* b) {
    asm volatile(
        "mma.sync.aligned.m16n8k8.row.col.f32.tf32.tf32.f32 "
        "{%0,%1,%2,%3}, {%4,%5,%6,%7}, {%8,%9}, {%0,%1,%2,%3};"
        : "+f"(c[0]), "+f"(c[1]), "+f"(c[2]), "+f"(c[3])
        : "r"(a[0]), "r"(a[1]), "r"(a[2]), "r"(a[3]), "r"(b[0]), "r"(b[1]));
}
__device__ __forceinline__ void cp16(uint32_t saddr, const void* gptr) {
    asm volatile("cp.async.cg.shared.global [%0], [%1], 16;" :: "r"(saddr), "l"(gptr));
}
__device__ __forceinline__ void cp_commit() { asm volatile("cp.async.commit_group;"); }
__device__ __forceinline__ void cp_wait1()  { asm volatile("cp.async.wait_group 1;"); }
__device__ __forceinline__ void cp_wait0()  { asm volatile("cp.async.wait_group 0;"); }

// --------------------------- tf32 rounding pass ------------------------------
__global__ void cvt_tf32_kernel(const float4* __restrict__ in, float4* __restrict__ out, int n4)
{
    for (int i = blockIdx.x * blockDim.x + threadIdx.x; i < n4; i += gridDim.x * blockDim.x) {
        float4 v = in[i];
        v.x = f2tf_f(v.x); v.y = f2tf_f(v.y); v.z = f2tf_f(v.z); v.w = f2tf_f(v.w);
        out[i] = v;
    }
}

// ============================================================================
// tf32 GEMM: C = alpha * A @ B^T (+bias +resid, relu, tf32-round output)
// A: [M,K] (lda), B: [N,K] (ldb), C: [M,N] (ldc). A,B pre-rounded to tf32.
// Block tile: 128 x (NF*16) x 32, 256 threads, 8 warps (4M x 2N),
// warp tile 32 x (NF*8). 2-stage cp.async pipeline, 2 CTAs/SM.
// ============================================================================
template<int NF>
__global__ __launch_bounds__(256, 2)
void mm_tf32(const float* __restrict__ A, const float* __restrict__ Bm,
             float* __restrict__ C, int K, int lda, int ldb, int ldc,
             long long sA1, long long sA2, long long sB1, long long sB2,
             long long sC1, long long sC2,
             float alpha, const float* __restrict__ bias,
             const float* __restrict__ resid, int ldres, int relu, int round_out)
{
    constexpr int BN   = NF * 16;
    constexpr int ASTG = 128 * 36;         // uint32 per stage (A part)
    constexpr int BSTG = BN * 36;
    constexpr int STG  = ASTG + BSTG;

    extern __shared__ uint32_t sm[];

    const int z = blockIdx.z;
    A  += (size_t)(z >> 3) * sA1 + (size_t)(z & 7) * sA2;
    Bm += (size_t)(z >> 3) * sB1 + (size_t)(z & 7) * sB2;
    C  += (size_t)(z >> 3) * sC1 + (size_t)(z & 7) * sC2;

    const int tid  = threadIdx.x;
    const int row0 = blockIdx.y * 128, col0 = blockIdx.x * BN;
    const int warp = tid >> 5, lane = tid & 31;
    const int wm = warp & 3, wn = warp >> 2;
    const int g = lane >> 2, tg = lane & 3;

    const uint32_t smb = (uint32_t)__cvta_generic_to_shared(sm);

    float acc[2][NF][4] = {};

    auto stage = [&](int st, int k0) {
        const uint32_t baseA = smb + (uint32_t)(st * STG) * 4u;
        const uint32_t baseB = baseA + (uint32_t)ASTG * 4u;
#pragma unroll
        for (int i = 0; i < 4; i++) {
            const int s = tid + i * 256, r = s >> 3, kq = s & 7;
            cp16(baseA + (uint32_t)(r * 36 + kq * 4) * 4u,
                 A + (size_t)(row0 + r) * lda + k0 + kq * 4);
        }
#pragma unroll
        for (int i = 0; i < NF / 2; i++) {
            const int s = tid + i * 256, r = s >> 3, kq = s & 7;
            cp16(baseB + (uint32_t)(r * 36 + kq * 4) * 4u,
                 Bm + (size_t)(col0 + r) * ldb + k0 + kq * 4);
        }
    };

    const int T = K >> 5;
    stage(0, 0);
    cp_commit();

    for (int t = 0; t < T; ++t) {
        if (t + 1 < T) { stage((t + 1) & 1, (t + 1) << 5); cp_commit(); cp_wait1(); }
        else           { cp_wait0(); }
        __syncthreads();

        const uint32_t* As = sm + (t & 1) * STG;
        const uint32_t* Bs = As + ASTG;

#pragma unroll
        for (int ks = 0; ks < 32; ks += 8) {
            uint32_t a[2][4], b[NF][2];
#pragma unroll
            for (int mf = 0; mf < 2; mf++) {
                const int m0 = wm * 32 + mf * 16;
                a[mf][0] = As[(m0 + g) * 36 + ks + tg];
                a[mf][1] = As[(m0 + 8 + g) * 36 + ks + tg];
                a[mf][2] = As[(m0 + g) * 36 + ks + 4 + tg];
                a[mf][3] = As[(m0 + 8 + g) * 36 + ks + 4 + tg];
            }
#pragma unroll
            for (int nf = 0; nf < NF; nf++) {
                const int n0 = wn * NF * 8 + nf * 8;
                b[nf][0] = Bs[(n0 + g) * 36 + ks + tg];
                b[nf][1] = Bs[(n0 + g) * 36 + ks + 4 + tg];
            }
#pragma unroll
            for (int mf = 0; mf < 2; mf++)
#pragma unroll
                for (int nf = 0; nf < NF; nf++)
                    mma8(acc[mf][nf], a[mf], b[nf]);
        }
        __syncthreads();
    }

#pragma unroll
    for (int mf = 0; mf < 2; mf++) {
#pragma unroll
        for (int nf = 0; nf < NF; nf++) {
            const int r = row0 + wm * 32 + mf * 16 + g;
            const int c = col0 + wn * NF * 8 + nf * 8 + 2 * tg;
#pragma unroll
            for (int q = 0; q < 4; q++) {
                const int rr = r + (q >> 1) * 8;
                const int cc = c + (q & 1);
                float v = acc[mf][nf][q] * alpha;
                if (bias)  v += bias[cc];
                if (resid) v += resid[(size_t)rr * ldres + cc];
                if (relu)  v = fmaxf(v, 0.f);
                if (round_out) v = f2tf_f(v);
                C[(size_t)rr * ldc + cc] = v;
            }
        }
    }
}

// ============================================================================
// PV: O[b, l, h*256+e] = P[z] @ V[z]  (z = b*8+h). Inputs pre-rounded.
// Vs staged [k][n] pitch 136; 2-stage cp.async; output tf32-rounded.
// ============================================================================
__global__ __launch_bounds__(256, 2)
void av_tf32(const float* __restrict__ P, const float* __restrict__ Vb,
             float* __restrict__ O)
{
    constexpr int ASTG = 128 * 36;
    constexpr int VSTG = 32 * 136;
    constexpr int STG  = ASTG + VSTG;
    extern __shared__ uint32_t sm[];

    const int z = blockIdx.z, b = z >> 3, h = z & 7;
    const float* A = P + (size_t)z * L_ * L_;
    const float* V = Vb + (size_t)b * L_ * HD_ + h * D_;

    const int tid  = threadIdx.x;
    const int row0 = blockIdx.y * 128, col0 = blockIdx.x * 128;
    const int warp = tid >> 5, lane = tid & 31;
    const int wm = warp & 3, wn = warp >> 2;
    const int g = lane >> 2, tg = lane & 3;

    const uint32_t smb = (uint32_t)__cvta_generic_to_shared(sm);

    float acc[2][8][4] = {};

    auto stage = [&](int st, int k0) {
        const uint32_t baseA = smb + (uint32_t)(st * STG) * 4u;
        const uint32_t baseV = baseA + (uint32_t)ASTG * 4u;
#pragma unroll
        for (int i = 0; i < 4; i++) {
            const int s = tid + i * 256, r = s >> 3, kq = s & 7;
            cp16(baseA + (uint32_t)(r * 36 + kq * 4) * 4u,
                 A + (size_t)(row0 + r) * L_ + k0 + kq * 4);
        }
#pragma unroll
        for (int i = 0; i < 4; i++) {
            const int s = tid + i * 256, j = s >> 5, eg = s & 31;
            cp16(baseV + (uint32_t)(j * 136 + eg * 4) * 4u,
                 V + (size_t)(k0 + j) * HD_ + col0 + eg * 4);
        }
    };

    const int T = L_ >> 5;
    stage(0, 0);
    cp_commit();

    for (int t = 0; t < T; ++t) {
        if (t + 1 < T) { stage((t + 1) & 1, (t + 1) << 5); cp_commit(); cp_wait1(); }
        else           { cp_wait0(); }
        __syncthreads();

        const uint32_t* As = sm + (t & 1) * STG;
        const uint32_t* Vs = As + ASTG;

#pragma unroll
        for (int ks = 0; ks < 32; ks += 8) {
            uint32_t a[2][4], bfr[8][2];
#pragma unroll
            for (int mf = 0; mf < 2; mf++) {
                const int m0 = wm * 32 + mf * 16;
                a[mf][0] = As[(m0 + g) * 36 + ks + tg];
                a[mf][1] = As[(m0 + 8 + g) * 36 + ks + tg];
                a[mf][2] = As[(m0 + g) * 36 + ks + 4 + tg];
                a[mf][3] = As[(m0 + 8 + g) * 36 + ks + 4 + tg];
            }
#pragma unroll
            for (int nf = 0; nf < 8; nf++) {
                const int n0 = wn * 64 + nf * 8;
                bfr[nf][0] = Vs[(ks + tg) * 136 + n0 + g];
                bfr[nf][1] = Vs[(ks + 4 + tg) * 136 + n0 + g];
            }
#pragma unroll
            for (int mf = 0; mf < 2; mf++)
#pragma unroll
                for (int nf = 0; nf < 8; nf++)
                    mma8(acc[mf][nf], a[mf], bfr[nf]);
        }
        __syncthreads();
    }

#pragma unroll
    for (int mf = 0; mf < 2; mf++) {
#pragma unroll
        for (int nf = 0; nf < 8; nf++) {
            const int r = row0 + wm * 32 + mf * 16 + g;
            const int c = col0 + wn * 64 + nf * 8 + 2 * tg;
#pragma unroll
            for (int q = 0; q < 4; q++) {
                const int rr = r + (q >> 1) * 8;
                const int cc = c + (q & 1);
                O[(size_t)(b * L_ + rr) * HD_ + h * D_ + cc] = f2tf_f(acc[mf][nf][q]);
            }
        }
    }
}

// --------------------------- softmax (rounds probs to tf32) ------------------
__global__ void softmax_kernel(float* __restrict__ S)
{
    __shared__ float red[8];
    const size_t row = blockIdx.x;
    float* p = S + row * (size_t)L_;
    const int t = threadIdx.x;

    float4 v = reinterpret_cast<float4*>(p)[t];
    float m = fmaxf(fmaxf(v.x, v.y), fmaxf(v.z, v.w));
#pragma unroll
    for (int o = 16; o; o >>= 1) m = fmaxf(m, __shfl_xor_sync(~0u, m, o));
    if ((t & 31) == 0) red[t >> 5] = m;
    __syncthreads();
    float mm = red[0];
#pragma unroll
    for (int i = 1; i < 8; i++) mm = fmaxf(mm, red[i]);
    __syncthreads();

    v.x = expf(v.x - mm); v.y = expf(v.y - mm);
    v.z = expf(v.z - mm); v.w = expf(v.w - mm);
    float s = v.x + v.y + v.z + v.w;
#pragma unroll
    for (int o = 16; o; o >>= 1) s += __shfl_xor_sync(~0u, s, o);
    if ((t & 31) == 0) red[t >> 5] = s;
    __syncthreads();
    float ss = 0.f;
#pragma unroll
    for (int i = 0; i < 8; i++) ss += red[i];
    const float inv = 1.f / ss;
    v.x = f2tf_f(v.x * inv); v.y = f2tf_f(v.y * inv);
    v.z = f2tf_f(v.z * inv); v.w = f2tf_f(v.w * inv);
    reinterpret_cast<float4*>(p)[t] = v;
}

// --------------------------- layernorm (exact out + optional rounded) --------
__global__ void ln_kernel(const float* __restrict__ in, float* __restrict__ out,
                          float* __restrict__ out_r,
                          const float* __restrict__ g, const float* __restrict__ be)
{
    __shared__ float r1[8], r2[8];
    const int row = blockIdx.x, t = threadIdx.x;
    const float v = in[(size_t)row * D_ + t];
    float s = v, q = v * v;
#pragma unroll
    for (int o = 16; o; o >>= 1) {
        s += __shfl_xor_sync(~0u, s, o);
        q += __shfl_xor_sync(~0u, q, o);
    }
    if ((t & 31) == 0) { r1[t >> 5] = s; r2[t >> 5] = q; }
    __syncthreads();
    float S = 0.f, Q = 0.f;
#pragma unroll
    for (int i = 0; i < 8; i++) { S += r1[i]; Q += r2[i]; }
    const float mean = S * (1.f / D_);
    const float var = Q * (1.f / D_) - mean * mean;
    const float y = (v - mean) * rsqrtf(var + EPS_) * g[t] + be[t];
    out[(size_t)row * D_ + t] = y;
    if (out_r) out_r[(size_t)row * D_ + t] = f2tf_f(y);
}

// --------------------------- launch ------------------------------------------
extern "C" void kernel_launch(void* const* d_in, const int* in_sizes, int n_in,
                              void* d_out, int out_size)
{
    const float* x   = (const float*)d_in[0];
    const float* Wq  = (const float*)d_in[1];
    const float* Wk  = (const float*)d_in[2];
    const float* Wv  = (const float*)d_in[3];
    const float* Wu  = (const float*)d_in[4];
    const float* bu  = (const float*)d_in[5];
    const float* W1  = (const float*)d_in[6];
    const float* b1  = (const float*)d_in[7];
    const float* W2  = (const float*)d_in[8];
    const float* b2  = (const float*)d_in[9];
    const float* g1  = (const float*)d_in[10];
    const float* be1 = (const float*)d_in[11];
    const float* g2  = (const float*)d_in[12];
    const float* be2 = (const float*)d_in[13];
    float* out = (float*)d_out;

    float *Qb, *Kb, *Vb, *S, *O, *R1, *Z1, *Z1r, *Hb, *F;
    float *xr, *Wqr, *Wkr, *Wvr, *Wur, *W1r, *W2r;
    cudaGetSymbolAddress((void**)&Qb, g_Q);
    cudaGetSymbolAddress((void**)&Kb, g_K);
    cudaGetSymbolAddress((void**)&Vb, g_V);
    cudaGetSymbolAddress((void**)&S,  g_S);
    cudaGetSymbolAddress((void**)&O,  g_O);
    cudaGetSymbolAddress((void**)&R1, g_R1);
    cudaGetSymbolAddress((void**)&Z1, g_Z1);
    cudaGetSymbolAddress((void**)&Z1r, g_Z1r);
    cudaGetSymbolAddress((void**)&Hb, g_Hb);
    cudaGetSymbolAddress((void**)&F,  g_F);
    cudaGetSymbolAddress((void**)&xr,  g_xr);
    cudaGetSymbolAddress((void**)&Wqr, g_Wqr);
    cudaGetSymbolAddress((void**)&Wkr, g_Wkr);
    cudaGetSymbolAddress((void**)&Wvr, g_Wvr);
    cudaGetSymbolAddress((void**)&Wur, g_Wur);
    cudaGetSymbolAddress((void**)&W1r, g_W1r);
    cudaGetSymbolAddress((void**)&W2r, g_W2r);

    // opt-in dynamic smem (idempotent; not captured as graph nodes)
    constexpr int SMEM8  = 2 * (128 * 36 + 128 * 36) * 4;   // 73728
    constexpr int SMEM4  = 2 * (128 * 36 + 64 * 36) * 4;    // 55296
    constexpr int SMEMAV = 2 * (128 * 36 + 32 * 136) * 4;   // 71680
    cudaFuncSetAttribute(mm_tf32<8>, cudaFuncAttributeMaxDynamicSharedMemorySize, SMEM8);
    cudaFuncSetAttribute(mm_tf32<4>, cudaFuncAttributeMaxDynamicSharedMemorySize, SMEM4);
    cudaFuncSetAttribute(av_tf32,    cudaFuncAttributeMaxDynamicSharedMemorySize, SMEMAV);

    // round inputs to tf32 copies
    cvt_tf32_kernel<<<512, 256>>>((const float4*)x,  (float4*)xr,  ROWS_ * D_ / 4);
    cvt_tf32_kernel<<<256, 256>>>((const float4*)Wq, (float4*)Wqr, HD_ * D_ / 4);
    cvt_tf32_kernel<<<256, 256>>>((const float4*)Wk, (float4*)Wkr, HD_ * D_ / 4);
    cvt_tf32_kernel<<<256, 256>>>((const float4*)Wv, (float4*)Wvr, HD_ * D_ / 4);
    cvt_tf32_kernel<<<256, 256>>>((const float4*)Wu, (float4*)Wur, D_ * HD_ / 4);
    cvt_tf32_kernel<<<128, 256>>>((const float4*)W1, (float4*)W1r, F_ * D_ / 4);
    cvt_tf32_kernel<<<128, 256>>>((const float4*)W2, (float4*)W2r, D_ * F_ / 4);

    const long long LL2 = (long long)L_ * L_;

    // QKV projections (outputs tf32-rounded)
    mm_tf32<8><<<dim3(HD_ / 128, ROWS_ / 128, 1), 256, SMEM8>>>(xr, Wqr, Qb, D_, D_, D_, HD_,
        0, 0, 0, 0, 0, 0, 1.f, nullptr, nullptr, 0, 0, 1);
    mm_tf32<8><<<dim3(HD_ / 128, ROWS_ / 128, 1), 256, SMEM8>>>(xr, Wkr, Kb, D_, D_, D_, HD_,
        0, 0, 0, 0, 0, 0, 1.f, nullptr, nullptr, 0, 0, 1);
    mm_tf32<8><<<dim3(HD_ / 128, ROWS_ / 128, 1), 256, SMEM8>>>(xr, Wvr, Vb, D_, D_, D_, HD_,
        0, 0, 0, 0, 0, 0, 1.f, nullptr, nullptr, 0, 0, 1);

    // scores: per (b,h) Q @ K^T / 16
    mm_tf32<8><<<dim3(L_ / 128, L_ / 128, B_ * H_), 256, SMEM8>>>(Qb, Kb, S, D_, HD_, HD_, L_,
        (long long)L_ * HD_, D_, (long long)L_ * HD_, D_, 8 * LL2, LL2,
        0.0625f, nullptr, nullptr, 0, 0, 0);

    softmax_kernel<<<B_ * H_ * L_, 256>>>(S);

    av_tf32<<<dim3(D_ / 128, L_ / 128, B_ * H_), 256, SMEMAV>>>(S, Vb, O);

    // output projection + bias + residual(x)  [BN=64 -> 256 CTAs]
    mm_tf32<4><<<dim3(D_ / 64, ROWS_ / 128, 1), 256, SMEM4>>>(O, Wur, R1, HD_, HD_, HD_, D_,
        0, 0, 0, 0, 0, 0, 1.f, bu, x, D_, 0, 0);
    ln_kernel<<<ROWS_, 256>>>(R1, Z1, Z1r, g1, be1);

    // FFN
    mm_tf32<8><<<dim3(F_ / 128, ROWS_ / 128, 1), 256, SMEM8>>>(Z1r, W1r, Hb, D_, D_, D_, F_,
        0, 0, 0, 0, 0, 0, 1.f, b1, nullptr, 0, 1, 1);
    mm_tf32<4><<<dim3(D_ / 64, ROWS_ / 128, 1), 256, SMEM4>>>(Hb, W2r, F, F_, F_, F_, D_,
        0, 0, 0, 0, 0, 0, 1.f, b2, Z1, D_, 0, 0);
    ln_kernel<<<ROWS_, 256>>>(F, out, nullptr, g2, be2);
}